// round 1
// baseline (speedup 1.0000x reference)
#include <cuda_runtime.h>
#include <cstdint>

#define NN 50000
#define NE 800000
#define DHID 256
#define DOUT 128
#define KDIM 256

// Scratch (allocation-free rule: __device__ globals)
__device__ float g_deg[NN];
__device__ float g_dinv[NN];
__device__ float g_xs1[(size_t)NN * DHID];
__device__ float g_agg1[(size_t)NN * DHID];
__device__ float g_h[(size_t)NN * DHID];
__device__ float g_xs2[(size_t)NN * DOUT];
__device__ float g_agg2[(size_t)NN * DOUT];

__global__ void k_deg_init() {
    int i = blockIdx.x * blockDim.x + threadIdx.x;
    if (i < NN) g_deg[i] = 1.0f;  // self-loop
}

__global__ void k_deg_count(const int* __restrict__ dst) {
    int i = blockIdx.x * blockDim.x + threadIdx.x;
    if (i < NE) atomicAdd(&g_deg[dst[i]], 1.0f);
}

__global__ void k_dinv() {
    int i = blockIdx.x * blockDim.x + threadIdx.x;
    if (i < NN) g_dinv[i] = rsqrtf(g_deg[i]);
}

// xs = (A[M,K] @ B[K,N]) * dinv[row]; also agg = xs (self-loop init).
template <int N>
__global__ void __launch_bounds__(256) k_gemm_scale(
    const float* __restrict__ A, const float* __restrict__ B,
    float* __restrict__ xs, float* __restrict__ agg, int M) {
    __shared__ float As[16][64];   // [k][m] (transposed on store)
    __shared__ float Bs[16][64];   // [k][n]
    int tid = threadIdx.x;
    int tx = tid & 15, ty = tid >> 4;
    int bm = blockIdx.x, bn = blockIdx.y;

    float acc[4][4] = {};

    int arow = tid >> 2, acol = (tid & 3) * 4;     // A: 64 rows x 16 k, float4 along K
    int brow = tid >> 4, bcol = (tid & 15) * 4;    // B: 16 k x 64 n, float4 along N
    int gr = bm * 64 + arow;
    const float* Aptr = A + (size_t)gr * KDIM + acol;
    const float* Bptr = B + (size_t)brow * N + bn * 64 + bcol;

    for (int kb = 0; kb < KDIM; kb += 16) {
        float4 av = make_float4(0.f, 0.f, 0.f, 0.f);
        if (gr < M) av = *(const float4*)(Aptr + kb);
        As[acol + 0][arow] = av.x;
        As[acol + 1][arow] = av.y;
        As[acol + 2][arow] = av.z;
        As[acol + 3][arow] = av.w;
        float4 bv = *(const float4*)(Bptr + (size_t)kb * N);
        *(float4*)&Bs[brow][bcol] = bv;
        __syncthreads();
#pragma unroll
        for (int k = 0; k < 16; k++) {
            float4 a4 = *(const float4*)&As[k][ty * 4];
            float4 b4 = *(const float4*)&Bs[k][tx * 4];
            float a[4] = {a4.x, a4.y, a4.z, a4.w};
            float b[4] = {b4.x, b4.y, b4.z, b4.w};
#pragma unroll
            for (int i = 0; i < 4; i++)
#pragma unroll
                for (int j = 0; j < 4; j++) acc[i][j] += a[i] * b[j];
        }
        __syncthreads();
    }

#pragma unroll
    for (int i = 0; i < 4; i++) {
        int row = bm * 64 + ty * 4 + i;
        if (row < M) {
            float dv = g_dinv[row];
            float4 v = make_float4(acc[i][0] * dv, acc[i][1] * dv,
                                   acc[i][2] * dv, acc[i][3] * dv);
            size_t off = (size_t)row * N + bn * 64 + tx * 4;
            *(float4*)(xs + off) = v;
            *(float4*)(agg + off) = v;
        }
    }
}

__device__ __forceinline__ void red_add4(float4* p, float4 v) {
    asm volatile("red.global.add.v4.f32 [%0], {%1,%2,%3,%4};"
                 :: "l"(p), "f"(v.x), "f"(v.y), "f"(v.z), "f"(v.w)
                 : "memory");
}

// agg[dst] += xs[src], one warp per edge, float4 lanes.
template <int D4>
__global__ void k_scatter(const int* __restrict__ src, const int* __restrict__ dst,
                          const float* __restrict__ xs, float* __restrict__ agg) {
    int w = (blockIdx.x * blockDim.x + threadIdx.x) >> 5;
    int lane = threadIdx.x & 31;
    if (w >= NE) return;
    int s = __ldg(&src[w]);
    int d = __ldg(&dst[w]);
    const float4* xr = (const float4*)xs + (size_t)s * D4;
    float4* ar = (float4*)agg + (size_t)d * D4;
#pragma unroll
    for (int i = 0; i < D4 / 32; i++) {
        float4 v = __ldg(&xr[lane + 32 * i]);
        red_add4(&ar[lane + 32 * i], v);
    }
}

// h = relu(dinv[row]*agg1 + b1)
__global__ void k_post1(const float* __restrict__ b1) {
    int idx = blockIdx.x * blockDim.x + threadIdx.x;  // float4 index
    if (idx >= NN * (DHID / 4)) return;
    int row = idx / (DHID / 4);
    int c = idx % (DHID / 4);
    float dv = g_dinv[row];
    float4 a = ((const float4*)g_agg1)[idx];
    float4 b = ((const float4*)b1)[c];
    float4 h;
    h.x = fmaxf(dv * a.x + b.x, 0.f);
    h.y = fmaxf(dv * a.y + b.y, 0.f);
    h.z = fmaxf(dv * a.z + b.z, 0.f);
    h.w = fmaxf(dv * a.w + b.w, 0.f);
    ((float4*)g_h)[idx] = h;
}

// out = dinv[row]*agg2 + b2
__global__ void k_final(const float* __restrict__ b2, float* __restrict__ out) {
    int idx = blockIdx.x * blockDim.x + threadIdx.x;
    if (idx >= NN * (DOUT / 4)) return;
    int row = idx / (DOUT / 4);
    int c = idx % (DOUT / 4);
    float dv = g_dinv[row];
    float4 a = ((const float4*)g_agg2)[idx];
    float4 b = ((const float4*)b2)[c];
    float4 o;
    o.x = dv * a.x + b.x;
    o.y = dv * a.y + b.y;
    o.z = dv * a.z + b.z;
    o.w = dv * a.w + b.w;
    ((float4*)out)[idx] = o;
}

extern "C" void kernel_launch(void* const* d_in, const int* in_sizes, int n_in,
                              void* d_out, int out_size) {
    const float* z  = (const float*)d_in[0];
    const int*   ei = (const int*)d_in[1];
    const float* W1 = (const float*)d_in[2];
    const float* b1 = (const float*)d_in[3];
    const float* W2 = (const float*)d_in[4];
    const float* b2 = (const float*)d_in[5];
    const int* src = ei;
    const int* dst = ei + NE;
    float* out = (float*)d_out;

    float *xs1, *agg1, *h, *xs2, *agg2;
    cudaGetSymbolAddress((void**)&xs1,  g_xs1);
    cudaGetSymbolAddress((void**)&agg1, g_agg1);
    cudaGetSymbolAddress((void**)&h,    g_h);
    cudaGetSymbolAddress((void**)&xs2,  g_xs2);
    cudaGetSymbolAddress((void**)&agg2, g_agg2);

    k_deg_init<<<(NN + 255) / 256, 256>>>();
    k_deg_count<<<(NE + 255) / 256, 256>>>(dst);
    k_dinv<<<(NN + 255) / 256, 256>>>();

    // Layer 1
    k_gemm_scale<DHID><<<dim3((NN + 63) / 64, DHID / 64), 256>>>(z, W1, xs1, agg1, NN);
    k_scatter<DHID / 4><<<(NE * 32 + 255) / 256, 256>>>(src, dst, xs1, agg1);
    k_post1<<<(NN * (DHID / 4) + 255) / 256, 256>>>(b1);

    // Layer 2
    k_gemm_scale<DOUT><<<dim3((NN + 63) / 64, DOUT / 64), 256>>>(h, W2, xs2, agg2, NN);
    k_scatter<DOUT / 4><<<(NE * 32 + 255) / 256, 256>>>(src, dst, xs2, agg2);
    k_final<<<(NN * (DOUT / 4) + 255) / 256, 256>>>(b2, out);
}

// round 2
// speedup vs baseline: 1.1708x; 1.1708x over previous
#include <cuda_runtime.h>
#include <cstdint>

#define NN 50000
#define NE 800000
#define DHID 256
#define DOUT 128
#define KDIM 256

// Scratch (allocation-free rule: __device__ globals)
__device__ int   g_deg[NN];
__device__ int   g_off[NN + 1];
__device__ int   g_cur[NN];
__device__ float g_dinv[NN];
__device__ int   g_esrc[NE];
__device__ float g_xs1[(size_t)NN * DHID];
__device__ float g_h[(size_t)NN * DHID];
__device__ float g_xs2[(size_t)NN * DOUT];

__global__ void k_deg_init() {
    int i = blockIdx.x * blockDim.x + threadIdx.x;
    if (i < NN) g_deg[i] = 0;
}

__global__ void k_deg_count(const int* __restrict__ dst) {
    int i = blockIdx.x * blockDim.x + threadIdx.x;
    if (i < NE) atomicAdd(&g_deg[dst[i]], 1);
}

// Single-block scan: exclusive offsets, cursor copy, dinv = rsqrt(deg+1).
__global__ void k_scan() {
    __shared__ int sh[1024];
    const int C = 49;  // 1024*49 >= 50000
    int t = threadIdx.x;
    int start = t * C;
    int stop = start + C < NN ? start + C : NN;
    int s = 0;
    for (int i = start; i < stop; i++) s += g_deg[i];
    sh[t] = s;
    __syncthreads();
    for (int d = 1; d < 1024; d <<= 1) {
        int add = (t >= d) ? sh[t - d] : 0;
        __syncthreads();
        sh[t] += add;
        __syncthreads();
    }
    int run = sh[t] - s;  // exclusive base
    for (int i = start; i < stop; i++) {
        g_off[i] = run;
        g_cur[i] = run;
        int dg = g_deg[i];
        run += dg;
        g_dinv[i] = rsqrtf((float)(dg + 1));
    }
    if (t == 0) g_off[NN] = NE;
}

__global__ void k_fill(const int* __restrict__ src, const int* __restrict__ dst) {
    int e = blockIdx.x * blockDim.x + threadIdx.x;
    if (e >= NE) return;
    int d = dst[e];
    int pos = atomicAdd(&g_cur[d], 1);
    g_esrc[pos] = src[e];
}

// xs = (A[M,256] @ B[256,N]) * dinv[row].  128x128 tile, 8x8 per thread.
template <int N>
__global__ void __launch_bounds__(256, 2) k_gemm(
    const float* __restrict__ A, const float* __restrict__ B,
    float* __restrict__ xs, int M) {
    __shared__ float As[8][128];  // [k][m]
    __shared__ float Bs[8][128];  // [k][n]
    int tid = threadIdx.x;
    int bm = blockIdx.x * 128;
    int bn = blockIdx.y * 128;

    int arow = tid >> 1, ak = (tid & 1) * 4;   // 128 rows x 8 k
    int brow = tid >> 5, bq = (tid & 31) * 4;  // 8 k x 128 n
    bool avalid = (bm + arow) < M;
    const float* Ap = A + (size_t)(bm + arow) * KDIM + ak;
    const float* Bp = B + (size_t)brow * N + bn + bq;

    int tx = tid & 15, ty = tid >> 4;
    int m0 = ty * 4, n0 = tx * 4;

    float acc[8][8] = {};

    for (int kb = 0; kb < KDIM; kb += 8) {
        float4 av = avalid ? *(const float4*)(Ap + kb) : make_float4(0.f, 0.f, 0.f, 0.f);
        float4 bv = *(const float4*)(Bp + (size_t)kb * N);
        __syncthreads();
        As[ak + 0][arow] = av.x;
        As[ak + 1][arow] = av.y;
        As[ak + 2][arow] = av.z;
        As[ak + 3][arow] = av.w;
        *(float4*)&Bs[brow][bq] = bv;
        __syncthreads();
#pragma unroll
        for (int k = 0; k < 8; k++) {
            float4 a0 = *(const float4*)&As[k][m0];
            float4 a1 = *(const float4*)&As[k][m0 + 64];
            float4 b0 = *(const float4*)&Bs[k][n0];
            float4 b1 = *(const float4*)&Bs[k][n0 + 64];
            float a[8] = {a0.x, a0.y, a0.z, a0.w, a1.x, a1.y, a1.z, a1.w};
            float b[8] = {b0.x, b0.y, b0.z, b0.w, b1.x, b1.y, b1.z, b1.w};
#pragma unroll
            for (int i = 0; i < 8; i++)
#pragma unroll
                for (int j = 0; j < 8; j++) acc[i][j] += a[i] * b[j];
        }
    }

#pragma unroll
    for (int mi = 0; mi < 2; mi++) {
#pragma unroll
        for (int i = 0; i < 4; i++) {
            int row = bm + m0 + mi * 64 + i;
            if (row < M) {
                float dv = g_dinv[row];
                int ai = mi * 4 + i;
                float4 v0 = make_float4(acc[ai][0] * dv, acc[ai][1] * dv,
                                        acc[ai][2] * dv, acc[ai][3] * dv);
                float4 v1 = make_float4(acc[ai][4] * dv, acc[ai][5] * dv,
                                        acc[ai][6] * dv, acc[ai][7] * dv);
                size_t off = (size_t)row * N + bn;
                *(float4*)(xs + off + n0) = v0;
                *(float4*)(xs + off + n0 + 64) = v1;
            }
        }
    }
}

// One warp per node: acc = xs[node] + sum_{in-edges} xs[src]; out = relu?(dinv*acc + b)
template <int D4, bool RELU>
__global__ void k_aggregate(const float* __restrict__ xs,
                            const float* __restrict__ bias,
                            float* __restrict__ outp) {
    int w = (blockIdx.x * blockDim.x + threadIdx.x) >> 5;
    int lane = threadIdx.x & 31;
    if (w >= NN) return;
    constexpr int R = D4 / 32;  // float4s per lane (2 for D=256, 1 for D=128)

    float4 acc[R], acc2[R];
    const float4* self = (const float4*)xs + (size_t)w * D4;
#pragma unroll
    for (int r = 0; r < R; r++) {
        acc[r] = __ldg(&self[lane + 32 * r]);
        acc2[r] = make_float4(0.f, 0.f, 0.f, 0.f);
    }

    int beg = g_off[w], end = g_off[w + 1];
    int i = beg;
    for (; i + 1 < end; i += 2) {
        int s0 = __ldg(&g_esrc[i]);
        int s1 = __ldg(&g_esrc[i + 1]);
        const float4* r0 = (const float4*)xs + (size_t)s0 * D4;
        const float4* r1 = (const float4*)xs + (size_t)s1 * D4;
#pragma unroll
        for (int r = 0; r < R; r++) {
            float4 v0 = __ldg(&r0[lane + 32 * r]);
            float4 v1 = __ldg(&r1[lane + 32 * r]);
            acc[r].x += v0.x; acc[r].y += v0.y; acc[r].z += v0.z; acc[r].w += v0.w;
            acc2[r].x += v1.x; acc2[r].y += v1.y; acc2[r].z += v1.z; acc2[r].w += v1.w;
        }
    }
    if (i < end) {
        int s0 = __ldg(&g_esrc[i]);
        const float4* r0 = (const float4*)xs + (size_t)s0 * D4;
#pragma unroll
        for (int r = 0; r < R; r++) {
            float4 v0 = __ldg(&r0[lane + 32 * r]);
            acc[r].x += v0.x; acc[r].y += v0.y; acc[r].z += v0.z; acc[r].w += v0.w;
        }
    }

    float dv = g_dinv[w];
    float4* orow = (float4*)outp + (size_t)w * D4;
#pragma unroll
    for (int r = 0; r < R; r++) {
        float4 b = __ldg((const float4*)bias + lane + 32 * r);
        float4 o;
        o.x = dv * (acc[r].x + acc2[r].x) + b.x;
        o.y = dv * (acc[r].y + acc2[r].y) + b.y;
        o.z = dv * (acc[r].z + acc2[r].z) + b.z;
        o.w = dv * (acc[r].w + acc2[r].w) + b.w;
        if (RELU) {
            o.x = fmaxf(o.x, 0.f); o.y = fmaxf(o.y, 0.f);
            o.z = fmaxf(o.z, 0.f); o.w = fmaxf(o.w, 0.f);
        }
        orow[lane + 32 * r] = o;
    }
}

extern "C" void kernel_launch(void* const* d_in, const int* in_sizes, int n_in,
                              void* d_out, int out_size) {
    const float* z  = (const float*)d_in[0];
    const int*   ei = (const int*)d_in[1];
    const float* W1 = (const float*)d_in[2];
    const float* b1 = (const float*)d_in[3];
    const float* W2 = (const float*)d_in[4];
    const float* b2 = (const float*)d_in[5];
    const int* src = ei;
    const int* dst = ei + NE;
    float* out = (float*)d_out;

    float *xs1, *h, *xs2;
    cudaGetSymbolAddress((void**)&xs1, g_xs1);
    cudaGetSymbolAddress((void**)&h,   g_h);
    cudaGetSymbolAddress((void**)&xs2, g_xs2);

    // CSR build
    k_deg_init<<<(NN + 255) / 256, 256>>>();
    k_deg_count<<<(NE + 255) / 256, 256>>>(dst);
    k_scan<<<1, 1024>>>();
    k_fill<<<(NE + 255) / 256, 256>>>(src, dst);

    // Layer 1
    k_gemm<DHID><<<dim3((NN + 127) / 128, DHID / 128), 256>>>(z, W1, xs1, NN);
    k_aggregate<DHID / 4, true><<<(NN * 32 + 255) / 256, 256>>>(xs1, b1, h);

    // Layer 2
    k_gemm<DOUT><<<dim3((NN + 127) / 128, DOUT / 128), 256>>>(h, W2, xs2, NN);
    k_aggregate<DOUT / 4, false><<<(NN * 32 + 255) / 256, 256>>>(xs2, b2, out);
}

// round 4
// speedup vs baseline: 1.5999x; 1.3665x over previous
#include <cuda_runtime.h>
#include <cuda_bf16.h>
#include <cstdint>

#define NN 50000
#define NE 800000
#define DHID 256
#define DOUT 128
#define KDIM 256

// ---------------- scratch (__device__ globals; no allocation allowed) -------
__device__ int   g_deg[NN];
__device__ int   g_off[NN + 1];
__device__ int   g_cur[NN];
__device__ float g_dinv[NN];
__device__ int   g_esrc[NE];
__device__ float g_xs1[(size_t)NN * DHID];
__device__ float g_h[(size_t)NN * DHID];
__device__ float g_xs2[(size_t)NN * DOUT];
__device__ __nv_bfloat16 g_w1h[KDIM * DHID];   // [n][k] transposed, bf16 hi
__device__ __nv_bfloat16 g_w1l[KDIM * DHID];   // bf16 lo
__device__ __nv_bfloat16 g_w2h[KDIM * DOUT];
__device__ __nv_bfloat16 g_w2l[KDIM * DOUT];

// ---------------- helpers ----------------------------------------------------
__device__ __forceinline__ uint32_t smem_u32(const void* p) {
    uint32_t a;
    asm("{ .reg .u64 t; cvta.to.shared.u64 t, %1; cvt.u32.u64 %0, t; }" : "=r"(a) : "l"(p));
    return a;
}
#define SW128(off) ((off) ^ (((off) >> 3) & 0x70))

__device__ __forceinline__ void cp_async16(uint32_t smem, const void* g) {
    asm volatile("cp.async.cg.shared.global [%0], [%1], 16;" :: "r"(smem), "l"(g));
}
__device__ __forceinline__ void cp_commit() {
    asm volatile("cp.async.commit_group;" ::: "memory");
}
template <int N>
__device__ __forceinline__ void cp_wait() {
    asm volatile("cp.async.wait_group %0;" :: "n"(N) : "memory");
}
__device__ __forceinline__ void ldsm_x4(uint32_t addr, uint32_t* r) {
    asm volatile("ldmatrix.sync.aligned.m8n8.x4.shared.b16 {%0,%1,%2,%3}, [%4];"
                 : "=r"(r[0]), "=r"(r[1]), "=r"(r[2]), "=r"(r[3]) : "r"(addr));
}
__device__ __forceinline__ void mma_bf16(float* d, const uint32_t* a, uint32_t b0, uint32_t b1) {
    asm volatile("mma.sync.aligned.m16n8k16.row.col.f32.bf16.bf16.f32 "
                 "{%0,%1,%2,%3}, {%4,%5,%6,%7}, {%8,%9}, {%0,%1,%2,%3};"
                 : "+f"(d[0]), "+f"(d[1]), "+f"(d[2]), "+f"(d[3])
                 : "r"(a[0]), "r"(a[1]), "r"(a[2]), "r"(a[3]), "r"(b0), "r"(b1));
}

// pack 4 floats into hi/lo bf16 pairs (each uint2 = 4 bf16)
__device__ __forceinline__ void split4(float4 v, uint2& hi, uint2& lo) {
    __nv_bfloat16 hx = __float2bfloat16(v.x), hy = __float2bfloat16(v.y);
    __nv_bfloat16 hz = __float2bfloat16(v.z), hw = __float2bfloat16(v.w);
    __nv_bfloat16 lx = __float2bfloat16(v.x - __bfloat162float(hx));
    __nv_bfloat16 ly = __float2bfloat16(v.y - __bfloat162float(hy));
    __nv_bfloat16 lz = __float2bfloat16(v.z - __bfloat162float(hz));
    __nv_bfloat16 lw = __float2bfloat16(v.w - __bfloat162float(hw));
    __nv_bfloat162 h0 = __nv_bfloat162(hx, hy), h1 = __nv_bfloat162(hz, hw);
    __nv_bfloat162 l0 = __nv_bfloat162(lx, ly), l1 = __nv_bfloat162(lz, lw);
    hi.x = *(uint32_t*)&h0; hi.y = *(uint32_t*)&h1;
    lo.x = *(uint32_t*)&l0; lo.y = *(uint32_t*)&l1;
}

// ---------------- CSR build --------------------------------------------------
__global__ void k_deg_init() {
    int i = blockIdx.x * blockDim.x + threadIdx.x;
    if (i < NN) g_deg[i] = 0;
}
__global__ void k_deg_count(const int* __restrict__ dst) {
    int i = blockIdx.x * blockDim.x + threadIdx.x;
    if (i < NE) atomicAdd(&g_deg[dst[i]], 1);
}
__global__ void k_scan() {
    __shared__ int sh[1024];
    const int C = 49;
    int t = threadIdx.x;
    int start = t * C;
    int stop = start + C < NN ? start + C : NN;
    int s = 0;
    for (int i = start; i < stop; i++) s += g_deg[i];
    sh[t] = s;
    __syncthreads();
    for (int d = 1; d < 1024; d <<= 1) {
        int add = (t >= d) ? sh[t - d] : 0;
        __syncthreads();
        sh[t] += add;
        __syncthreads();
    }
    int run = sh[t] - s;
    for (int i = start; i < stop; i++) {
        g_off[i] = run;
        g_cur[i] = run;
        int dg = g_deg[i];
        run += dg;
        g_dinv[i] = rsqrtf((float)(dg + 1));
    }
    if (t == 0) g_off[NN] = NE;
}
__global__ void k_fill(const int* __restrict__ src, const int* __restrict__ dst) {
    int e = blockIdx.x * blockDim.x + threadIdx.x;
    if (e >= NE) return;
    int d = dst[e];
    int pos = atomicAdd(&g_cur[d], 1);
    g_esrc[pos] = src[e];
}

// ---------------- weight transpose + bf16 split -------------------------------
__global__ void k_prepW(const float* __restrict__ W1, const float* __restrict__ W2) {
    int i = blockIdx.x * blockDim.x + threadIdx.x;
    if (i < KDIM * DHID) {
        int k = i >> 8, n = i & 255;
        float v = W1[i];
        __nv_bfloat16 hb = __float2bfloat16(v);
        g_w1h[n * KDIM + k] = hb;
        g_w1l[n * KDIM + k] = __float2bfloat16(v - __bfloat162float(hb));
    }
    int j = i - KDIM * DHID;
    if (j >= 0 && j < KDIM * DOUT) {
        int k = j >> 7, n = j & 127;
        float v = W2[j];
        __nv_bfloat16 hb = __float2bfloat16(v);
        g_w2h[n * KDIM + k] = hb;
        g_w2l[n * KDIM + k] = __float2bfloat16(v - __bfloat162float(hb));
    }
}

// ---------------- mma.sync bf16-split GEMM: xs = (A @ B^T)*dinv ---------------
// CTA 128x128, 8 warps (4m x 2n), warp tile 32m x 64n. K chunks of 64, double buf.
// Stage layout (bf16): Ah[128][64] @0, Al @16K, Bh[128][64] @32K, Bl @48K. Stage 64KB.
#define STAGE 65536
#define SMEM_DYN (2 * STAGE)

template <int NTOT>
__global__ void __launch_bounds__(256, 1) k_gemm_mma(
    const float* __restrict__ A, const __nv_bfloat16* __restrict__ Bhg,
    const __nv_bfloat16* __restrict__ Blg, float* __restrict__ xs, int M) {
    extern __shared__ char smraw[];
    uint32_t sb = smem_u32(smraw);
    int tid = threadIdx.x;
    int wid = tid >> 5, lane = tid & 31;
    int wm = wid & 3, wn = wid >> 2;              // warp grid 4m x 2n
    int bm = blockIdx.x * 128;
    int bn = blockIdx.y * 128;

    float acc[2][8][4];
#pragma unroll
    for (int a = 0; a < 2; a++)
#pragma unroll
        for (int b = 0; b < 8; b++)
#pragma unroll
            for (int c = 0; c < 4; c++) acc[a][b][c] = 0.f;

    // B chunk cp.async issue (hi+lo): 128 rows x 8 x 16B each
    auto issueB = [&](int c, uint32_t stage) {
#pragma unroll
        for (int i = 0; i < 4; i++) {
            int task = i * 256 + tid;            // 0..1023
            int row = task >> 3;
            int u = task & 7;
            uint32_t off = SW128((uint32_t)(row * 128 + u * 16));
            size_t gsrc = (size_t)(bn + row) * KDIM + c * 64 + u * 8;
            cp_async16(stage + 32768 + off, Bhg + gsrc);
            cp_async16(stage + 49152 + off, Blg + gsrc);
        }
    };
    // A chunk: fp32 gmem -> split bf16 -> smem (copy loop, no long-held regs)
    auto copyA = [&](int c, uint32_t stage) {
#pragma unroll
        for (int i = 0; i < 8; i++) {
            int task = i * 256 + tid;            // 0..2047
            int row = task >> 4;                 // 0..127
            int c4 = task & 15;                  // float4 within 64-float row
            float4 v = make_float4(0.f, 0.f, 0.f, 0.f);
            if (bm + row < M)
                v = *(const float4*)(A + (size_t)(bm + row) * KDIM + c * 64 + c4 * 4);
            uint2 hi, lo;
            split4(v, hi, lo);
            uint32_t off = SW128((uint32_t)(row * 128 + c4 * 8));
            *(uint2*)(smraw + (stage - sb) + off) = hi;
            *(uint2*)(smraw + (stage - sb) + 16384 + off) = lo;
        }
    };

    issueB(0, sb);
    cp_commit();

    for (int c = 0; c < 4; c++) {
        uint32_t stage = sb + (uint32_t)(c & 1) * STAGE;
        copyA(c, stage);
        if (c < 3) {
            issueB(c + 1, sb + (uint32_t)((c + 1) & 1) * STAGE);
            cp_commit();
            cp_wait<1>();
        } else {
            cp_wait<0>();
        }
        __syncthreads();

        // compute chunk c: 4 ksteps of 16
#pragma unroll
        for (int ks = 0; ks < 4; ks++) {
            uint32_t ah[2][4], al[2][4];
            uint32_t acol = (uint32_t)(ks * 32 + (lane >> 4) * 16);
#pragma unroll
            for (int mt = 0; mt < 2; mt++) {
                uint32_t arow = (uint32_t)(wm * 32 + mt * 16 + (lane & 15));
                uint32_t aoff = SW128(arow * 128 + acol);
                ldsm_x4(stage + aoff, ah[mt]);
                ldsm_x4(stage + 16384 + aoff, al[mt]);
            }
            uint32_t bcol = (uint32_t)(ks * 32 + ((lane >> 3) & 1) * 16);
#pragma unroll
            for (int p = 0; p < 4; p++) {        // n-tile pairs (16 n each)
                uint32_t brow = (uint32_t)(wn * 64 + p * 16 + (lane & 7) + ((lane >> 4) << 3));
                uint32_t boff = SW128(brow * 128 + bcol);
                uint32_t bh[4], bl[4];
                ldsm_x4(stage + 32768 + boff, bh);
                ldsm_x4(stage + 49152 + boff, bl);
#pragma unroll
                for (int mt = 0; mt < 2; mt++) {
#pragma unroll
                    for (int q = 0; q < 2; q++) {
                        float* d = acc[mt][p * 2 + q];
                        mma_bf16(d, ah[mt], bh[2 * q], bh[2 * q + 1]);
                        mma_bf16(d, al[mt], bh[2 * q], bh[2 * q + 1]);
                        mma_bf16(d, ah[mt], bl[2 * q], bl[2 * q + 1]);
                    }
                }
            }
        }
        if (c < 3) __syncthreads();
    }

    // epilogue: scale by dinv, store
#pragma unroll
    for (int mt = 0; mt < 2; mt++) {
        int r0 = bm + wm * 32 + mt * 16 + (lane >> 2);
        int r1 = r0 + 8;
        float dv0 = (r0 < M) ? g_dinv[r0] : 0.f;
        float dv1 = (r1 < M) ? g_dinv[r1] : 0.f;
#pragma unroll
        for (int nt = 0; nt < 8; nt++) {
            int col = bn + wn * 64 + nt * 8 + (lane & 3) * 2;
            float* d = acc[mt][nt];
            if (r0 < M) *(float2*)(xs + (size_t)r0 * NTOT + col) = make_float2(d[0] * dv0, d[1] * dv0);
            if (r1 < M) *(float2*)(xs + (size_t)r1 * NTOT + col) = make_float2(d[2] * dv1, d[3] * dv1);
        }
    }
}

// ---------------- CSR aggregate (one warp per node) --------------------------
template <int D4, bool RELU>
__global__ void k_aggregate(const float* __restrict__ xs,
                            const float* __restrict__ bias,
                            float* __restrict__ outp) {
    int w = (blockIdx.x * blockDim.x + threadIdx.x) >> 5;
    int lane = threadIdx.x & 31;
    if (w >= NN) return;
    constexpr int R = D4 / 32;

    float4 acc[R], acc2[R];
    const float4* self = (const float4*)xs + (size_t)w * D4;
#pragma unroll
    for (int r = 0; r < R; r++) {
        acc[r] = __ldg(&self[lane + 32 * r]);
        acc2[r] = make_float4(0.f, 0.f, 0.f, 0.f);
    }

    int beg = g_off[w], end = g_off[w + 1];
    int i = beg;
    for (; i + 1 < end; i += 2) {
        int s0 = __ldg(&g_esrc[i]);
        int s1 = __ldg(&g_esrc[i + 1]);
        const float4* r0 = (const float4*)xs + (size_t)s0 * D4;
        const float4* r1 = (const float4*)xs + (size_t)s1 * D4;
#pragma unroll
        for (int r = 0; r < R; r++) {
            float4 v0 = __ldg(&r0[lane + 32 * r]);
            float4 v1 = __ldg(&r1[lane + 32 * r]);
            acc[r].x += v0.x; acc[r].y += v0.y; acc[r].z += v0.z; acc[r].w += v0.w;
            acc2[r].x += v1.x; acc2[r].y += v1.y; acc2[r].z += v1.z; acc2[r].w += v1.w;
        }
    }
    if (i < end) {
        int s0 = __ldg(&g_esrc[i]);
        const float4* r0 = (const float4*)xs + (size_t)s0 * D4;
#pragma unroll
        for (int r = 0; r < R; r++) {
            float4 v0 = __ldg(&r0[lane + 32 * r]);
            acc[r].x += v0.x; acc[r].y += v0.y; acc[r].z += v0.z; acc[r].w += v0.w;
        }
    }

    float dv = g_dinv[w];
    float4* orow = (float4*)outp + (size_t)w * D4;
#pragma unroll
    for (int r = 0; r < R; r++) {
        float4 b = __ldg((const float4*)bias + lane + 32 * r);
        float4 o;
        o.x = dv * (acc[r].x + acc2[r].x) + b.x;
        o.y = dv * (acc[r].y + acc2[r].y) + b.y;
        o.z = dv * (acc[r].z + acc2[r].z) + b.z;
        o.w = dv * (acc[r].w + acc2[r].w) + b.w;
        if (RELU) {
            o.x = fmaxf(o.x, 0.f); o.y = fmaxf(o.y, 0.f);
            o.z = fmaxf(o.z, 0.f); o.w = fmaxf(o.w, 0.f);
        }
        orow[lane + 32 * r] = o;
    }
}

// ---------------- launch ------------------------------------------------------
extern "C" void kernel_launch(void* const* d_in, const int* in_sizes, int n_in,
                              void* d_out, int out_size) {
    const float* z  = (const float*)d_in[0];
    const int*   ei = (const int*)d_in[1];
    const float* W1 = (const float*)d_in[2];
    const float* b1 = (const float*)d_in[3];
    const float* W2 = (const float*)d_in[4];
    const float* b2 = (const float*)d_in[5];
    const int* src = ei;
    const int* dst = ei + NE;
    float* out = (float*)d_out;

    float *xs1, *h, *xs2;
    __nv_bfloat16 *w1h, *w1l, *w2h, *w2l;
    cudaGetSymbolAddress((void**)&xs1, g_xs1);
    cudaGetSymbolAddress((void**)&h,   g_h);
    cudaGetSymbolAddress((void**)&xs2, g_xs2);
    cudaGetSymbolAddress((void**)&w1h, g_w1h);
    cudaGetSymbolAddress((void**)&w1l, g_w1l);
    cudaGetSymbolAddress((void**)&w2h, g_w2h);
    cudaGetSymbolAddress((void**)&w2l, g_w2l);

    cudaFuncSetAttribute(k_gemm_mma<DHID>, cudaFuncAttributeMaxDynamicSharedMemorySize, SMEM_DYN);
    cudaFuncSetAttribute(k_gemm_mma<DOUT>, cudaFuncAttributeMaxDynamicSharedMemorySize, SMEM_DYN);

    // CSR build + weight prep
    k_deg_init<<<(NN + 255) / 256, 256>>>();
    k_deg_count<<<(NE + 255) / 256, 256>>>(dst);
    k_scan<<<1, 1024>>>();
    k_fill<<<(NE + 255) / 256, 256>>>(src, dst);
    k_prepW<<<(KDIM * DHID + KDIM * DOUT + 255) / 256, 256>>>(W1, W2);

    // Layer 1
    k_gemm_mma<DHID><<<dim3((NN + 127) / 128, DHID / 128), 256, SMEM_DYN>>>(z, w1h, w1l, xs1, NN);
    k_aggregate<DHID / 4, true><<<(NN * 32 + 255) / 256, 256>>>(xs1, b1, h);

    // Layer 2
    k_gemm_mma<DOUT><<<dim3((NN + 127) / 128, DOUT / 128), 256, SMEM_DYN>>>(h, w2h, w2l, xs2, NN);
    k_aggregate<DOUT / 4, false><<<(NN * 32 + 255) / 256, 256>>>(xs2, b2, out);
}

// round 5
// speedup vs baseline: 1.9943x; 1.2465x over previous
#include <cuda_runtime.h>
#include <cuda_bf16.h>
#include <cstdint>

#define NN 50000
#define NE 800000
#define DHID 256
#define DOUT 128
#define KDIM 256

// ---------------- scratch (__device__ globals; no allocation allowed) -------
__device__ int   g_deg[NN];
__device__ int   g_off[NN + 1];
__device__ int   g_cur[NN];
__device__ float g_dinv[NN];
__device__ int   g_esrc[NE];
__device__ float g_xs1[(size_t)NN * DHID];
__device__ float g_h[(size_t)NN * DHID];
__device__ float g_xs2[(size_t)NN * DOUT];
__device__ __nv_bfloat16 g_w1h[KDIM * DHID];   // [n][k] transposed, bf16 hi
__device__ __nv_bfloat16 g_w1l[KDIM * DHID];   // bf16 lo
__device__ __nv_bfloat16 g_w2h[KDIM * DOUT];
__device__ __nv_bfloat16 g_w2l[KDIM * DOUT];

// ---------------- helpers ----------------------------------------------------
__device__ __forceinline__ uint32_t smem_u32(const void* p) {
    uint32_t a;
    asm("{ .reg .u64 t; cvta.to.shared.u64 t, %1; cvt.u32.u64 %0, t; }" : "=r"(a) : "l"(p));
    return a;
}
#define SW128(off) ((off) ^ (((off) >> 3) & 0x70))

__device__ __forceinline__ void cp_async16(uint32_t smem, const void* g) {
    asm volatile("cp.async.cg.shared.global [%0], [%1], 16;" :: "r"(smem), "l"(g));
}
__device__ __forceinline__ void cp_commit() {
    asm volatile("cp.async.commit_group;" ::: "memory");
}
template <int N>
__device__ __forceinline__ void cp_wait() {
    asm volatile("cp.async.wait_group %0;" :: "n"(N) : "memory");
}
__device__ __forceinline__ void ldsm_x4(uint32_t addr, uint32_t* r) {
    asm volatile("ldmatrix.sync.aligned.m8n8.x4.shared.b16 {%0,%1,%2,%3}, [%4];"
                 : "=r"(r[0]), "=r"(r[1]), "=r"(r[2]), "=r"(r[3]) : "r"(addr));
}
__device__ __forceinline__ void mma_bf16(float* d, const uint32_t* a, uint32_t b0, uint32_t b1) {
    asm volatile("mma.sync.aligned.m16n8k16.row.col.f32.bf16.bf16.f32 "
                 "{%0,%1,%2,%3}, {%4,%5,%6,%7}, {%8,%9}, {%0,%1,%2,%3};"
                 : "+f"(d[0]), "+f"(d[1]), "+f"(d[2]), "+f"(d[3])
                 : "r"(a[0]), "r"(a[1]), "r"(a[2]), "r"(a[3]), "r"(b0), "r"(b1));
}

__device__ __forceinline__ void split4(float4 v, uint2& hi, uint2& lo) {
    __nv_bfloat16 hx = __float2bfloat16(v.x), hy = __float2bfloat16(v.y);
    __nv_bfloat16 hz = __float2bfloat16(v.z), hw = __float2bfloat16(v.w);
    __nv_bfloat16 lx = __float2bfloat16(v.x - __bfloat162float(hx));
    __nv_bfloat16 ly = __float2bfloat16(v.y - __bfloat162float(hy));
    __nv_bfloat16 lz = __float2bfloat16(v.z - __bfloat162float(hz));
    __nv_bfloat16 lw = __float2bfloat16(v.w - __bfloat162float(hw));
    __nv_bfloat162 h0 = __nv_bfloat162(hx, hy), h1 = __nv_bfloat162(hz, hw);
    __nv_bfloat162 l0 = __nv_bfloat162(lx, ly), l1 = __nv_bfloat162(lz, lw);
    hi.x = *(uint32_t*)&h0; hi.y = *(uint32_t*)&h1;
    lo.x = *(uint32_t*)&l0; lo.y = *(uint32_t*)&l1;
}

// ---------------- CSR build --------------------------------------------------
__global__ void k_deg_count(const int* __restrict__ dst) {
    int i = blockIdx.x * blockDim.x + threadIdx.x;
    if (i < NE) atomicAdd(&g_deg[dst[i]], 1);
}
__global__ void k_scan() {
    __shared__ int sh[1024];
    const int C = 49;
    int t = threadIdx.x;
    int start = t * C;
    int stop = start + C < NN ? start + C : NN;
    int s = 0;
    for (int i = start; i < stop; i++) s += g_deg[i];
    sh[t] = s;
    __syncthreads();
    for (int d = 1; d < 1024; d <<= 1) {
        int add = (t >= d) ? sh[t - d] : 0;
        __syncthreads();
        sh[t] += add;
        __syncthreads();
    }
    int run = sh[t] - s;
    for (int i = start; i < stop; i++) {
        g_off[i] = run;
        g_cur[i] = run;
        int dg = g_deg[i];
        run += dg;
        g_dinv[i] = rsqrtf((float)(dg + 1));
    }
    if (t == 0) g_off[NN] = NE;
}
__global__ void k_fill(const int* __restrict__ src, const int* __restrict__ dst) {
    int e = blockIdx.x * blockDim.x + threadIdx.x;
    if (e >= NE) return;
    int d = dst[e];
    int pos = atomicAdd(&g_cur[d], 1);
    g_esrc[pos] = src[e];
}

// ---------------- weight transpose + bf16 split -------------------------------
__global__ void k_prepW(const float* __restrict__ W1, const float* __restrict__ W2) {
    int i = blockIdx.x * blockDim.x + threadIdx.x;
    if (i < KDIM * DHID) {
        int k = i >> 8, n = i & 255;
        float v = W1[i];
        __nv_bfloat16 hb = __float2bfloat16(v);
        g_w1h[n * KDIM + k] = hb;
        g_w1l[n * KDIM + k] = __float2bfloat16(v - __bfloat162float(hb));
    }
    int j = i - KDIM * DHID;
    if (j >= 0 && j < KDIM * DOUT) {
        int k = j >> 7, n = j & 127;
        float v = W2[j];
        __nv_bfloat16 hb = __float2bfloat16(v);
        g_w2h[n * KDIM + k] = hb;
        g_w2l[n * KDIM + k] = __float2bfloat16(v - __bfloat162float(hb));
    }
}

// ---------------- mma.sync bf16-split GEMM: xs = A @ B^T (raw, no dinv) -------
#define STAGE 65536
#define SMEM_DYN (2 * STAGE)

template <int NTOT>
__global__ void __launch_bounds__(256, 1) k_gemm_mma(
    const float* __restrict__ A, const __nv_bfloat16* __restrict__ Bhg,
    const __nv_bfloat16* __restrict__ Blg, float* __restrict__ xs, int M) {
    extern __shared__ char smraw[];
    uint32_t sb = smem_u32(smraw);
    int tid = threadIdx.x;
    int wid = tid >> 5, lane = tid & 31;
    int wm = wid & 3, wn = wid >> 2;
    int bm = blockIdx.x * 128;
    int bn = blockIdx.y * 128;

    float acc[2][8][4];
#pragma unroll
    for (int a = 0; a < 2; a++)
#pragma unroll
        for (int b = 0; b < 8; b++)
#pragma unroll
            for (int c = 0; c < 4; c++) acc[a][b][c] = 0.f;

    auto issueB = [&](int c, uint32_t stage) {
#pragma unroll
        for (int i = 0; i < 4; i++) {
            int task = i * 256 + tid;
            int row = task >> 3;
            int u = task & 7;
            uint32_t off = SW128((uint32_t)(row * 128 + u * 16));
            size_t gsrc = (size_t)(bn + row) * KDIM + c * 64 + u * 8;
            cp_async16(stage + 32768 + off, Bhg + gsrc);
            cp_async16(stage + 49152 + off, Blg + gsrc);
        }
    };
    auto copyA = [&](int c, uint32_t stage) {
#pragma unroll
        for (int i = 0; i < 8; i++) {
            int task = i * 256 + tid;
            int row = task >> 4;
            int c4 = task & 15;
            float4 v = make_float4(0.f, 0.f, 0.f, 0.f);
            if (bm + row < M)
                v = *(const float4*)(A + (size_t)(bm + row) * KDIM + c * 64 + c4 * 4);
            uint2 hi, lo;
            split4(v, hi, lo);
            uint32_t off = SW128((uint32_t)(row * 128 + c4 * 8));
            *(uint2*)(smraw + (stage - sb) + off) = hi;
            *(uint2*)(smraw + (stage - sb) + 16384 + off) = lo;
        }
    };

    issueB(0, sb);
    cp_commit();

    for (int c = 0; c < 4; c++) {
        uint32_t stage = sb + (uint32_t)(c & 1) * STAGE;
        copyA(c, stage);
        if (c < 3) {
            issueB(c + 1, sb + (uint32_t)((c + 1) & 1) * STAGE);
            cp_commit();
            cp_wait<1>();
        } else {
            cp_wait<0>();
        }
        __syncthreads();

#pragma unroll
        for (int ks = 0; ks < 4; ks++) {
            uint32_t ah[2][4], al[2][4];
            uint32_t acol = (uint32_t)(ks * 32 + (lane >> 4) * 16);
#pragma unroll
            for (int mt = 0; mt < 2; mt++) {
                uint32_t arow = (uint32_t)(wm * 32 + mt * 16 + (lane & 15));
                uint32_t aoff = SW128(arow * 128 + acol);
                ldsm_x4(stage + aoff, ah[mt]);
                ldsm_x4(stage + 16384 + aoff, al[mt]);
            }
            uint32_t bcol = (uint32_t)(ks * 32 + ((lane >> 3) & 1) * 16);
#pragma unroll
            for (int p = 0; p < 4; p++) {
                uint32_t brow = (uint32_t)(wn * 64 + p * 16 + (lane & 7) + ((lane >> 4) << 3));
                uint32_t boff = SW128(brow * 128 + bcol);
                uint32_t bh[4], bl[4];
                ldsm_x4(stage + 32768 + boff, bh);
                ldsm_x4(stage + 49152 + boff, bl);
#pragma unroll
                for (int mt = 0; mt < 2; mt++) {
#pragma unroll
                    for (int q = 0; q < 2; q++) {
                        float* d = acc[mt][p * 2 + q];
                        mma_bf16(d, ah[mt], bh[2 * q], bh[2 * q + 1]);
                        mma_bf16(d, al[mt], bh[2 * q], bh[2 * q + 1]);
                        mma_bf16(d, ah[mt], bl[2 * q], bl[2 * q + 1]);
                    }
                }
            }
        }
        if (c < 3) __syncthreads();
    }

#pragma unroll
    for (int mt = 0; mt < 2; mt++) {
        int r0 = bm + wm * 32 + mt * 16 + (lane >> 2);
        int r1 = r0 + 8;
#pragma unroll
        for (int nt = 0; nt < 8; nt++) {
            int col = bn + wn * 64 + nt * 8 + (lane & 3) * 2;
            float* d = acc[mt][nt];
            if (r0 < M) *(float2*)(xs + (size_t)r0 * NTOT + col) = make_float2(d[0], d[1]);
            if (r1 < M) *(float2*)(xs + (size_t)r1 * NTOT + col) = make_float2(d[2], d[3]);
        }
    }
}

// ---------------- CSR aggregate (one warp per node, dinv applied here) --------
template <int D4, bool RELU>
__global__ void k_aggregate(const float* __restrict__ xs,
                            const float* __restrict__ bias,
                            float* __restrict__ outp) {
    int w = (blockIdx.x * blockDim.x + threadIdx.x) >> 5;
    int lane = threadIdx.x & 31;
    if (w >= NN) return;
    constexpr int R = D4 / 32;

    float dvw = g_dinv[w];
    float4 acc[R], acc2[R];
    const float4* self = (const float4*)xs + (size_t)w * D4;
#pragma unroll
    for (int r = 0; r < R; r++) {
        float4 sv = __ldg(&self[lane + 32 * r]);
        acc[r] = make_float4(sv.x * dvw, sv.y * dvw, sv.z * dvw, sv.w * dvw);
        acc2[r] = make_float4(0.f, 0.f, 0.f, 0.f);
    }

    int beg = g_off[w], end = g_off[w + 1];
    int i = beg;
    for (; i + 1 < end; i += 2) {
        int s0 = __ldg(&g_esrc[i]);
        int s1 = __ldg(&g_esrc[i + 1]);
        float ds0 = __ldg(&g_dinv[s0]);
        float ds1 = __ldg(&g_dinv[s1]);
        const float4* r0 = (const float4*)xs + (size_t)s0 * D4;
        const float4* r1 = (const float4*)xs + (size_t)s1 * D4;
#pragma unroll
        for (int r = 0; r < R; r++) {
            float4 v0 = __ldg(&r0[lane + 32 * r]);
            float4 v1 = __ldg(&r1[lane + 32 * r]);
            acc[r].x = fmaf(v0.x, ds0, acc[r].x);
            acc[r].y = fmaf(v0.y, ds0, acc[r].y);
            acc[r].z = fmaf(v0.z, ds0, acc[r].z);
            acc[r].w = fmaf(v0.w, ds0, acc[r].w);
            acc2[r].x = fmaf(v1.x, ds1, acc2[r].x);
            acc2[r].y = fmaf(v1.y, ds1, acc2[r].y);
            acc2[r].z = fmaf(v1.z, ds1, acc2[r].z);
            acc2[r].w = fmaf(v1.w, ds1, acc2[r].w);
        }
    }
    if (i < end) {
        int s0 = __ldg(&g_esrc[i]);
        float ds0 = __ldg(&g_dinv[s0]);
        const float4* r0 = (const float4*)xs + (size_t)s0 * D4;
#pragma unroll
        for (int r = 0; r < R; r++) {
            float4 v0 = __ldg(&r0[lane + 32 * r]);
            acc[r].x = fmaf(v0.x, ds0, acc[r].x);
            acc[r].y = fmaf(v0.y, ds0, acc[r].y);
            acc[r].z = fmaf(v0.z, ds0, acc[r].z);
            acc[r].w = fmaf(v0.w, ds0, acc[r].w);
        }
    }

    float4* orow = (float4*)outp + (size_t)w * D4;
#pragma unroll
    for (int r = 0; r < R; r++) {
        float4 b = __ldg((const float4*)bias + lane + 32 * r);
        float4 o;
        o.x = dvw * (acc[r].x + acc2[r].x) + b.x;
        o.y = dvw * (acc[r].y + acc2[r].y) + b.y;
        o.z = dvw * (acc[r].z + acc2[r].z) + b.z;
        o.w = dvw * (acc[r].w + acc2[r].w) + b.w;
        if (RELU) {
            o.x = fmaxf(o.x, 0.f); o.y = fmaxf(o.y, 0.f);
            o.z = fmaxf(o.z, 0.f); o.w = fmaxf(o.w, 0.f);
        }
        orow[lane + 32 * r] = o;
    }
}

// ---------------- launch ------------------------------------------------------
extern "C" void kernel_launch(void* const* d_in, const int* in_sizes, int n_in,
                              void* d_out, int out_size) {
    const float* z  = (const float*)d_in[0];
    const int*   ei = (const int*)d_in[1];
    const float* W1 = (const float*)d_in[2];
    const float* b1 = (const float*)d_in[3];
    const float* W2 = (const float*)d_in[4];
    const float* b2 = (const float*)d_in[5];
    const int* src = ei;
    const int* dst = ei + NE;
    float* out = (float*)d_out;

    float *xs1, *h, *xs2;
    int* degp;
    __nv_bfloat16 *w1h, *w1l, *w2h, *w2l;
    cudaGetSymbolAddress((void**)&xs1, g_xs1);
    cudaGetSymbolAddress((void**)&h,   g_h);
    cudaGetSymbolAddress((void**)&xs2, g_xs2);
    cudaGetSymbolAddress((void**)&degp, g_deg);
    cudaGetSymbolAddress((void**)&w1h, g_w1h);
    cudaGetSymbolAddress((void**)&w1l, g_w1l);
    cudaGetSymbolAddress((void**)&w2h, g_w2h);
    cudaGetSymbolAddress((void**)&w2l, g_w2l);

    cudaFuncSetAttribute(k_gemm_mma<DHID>, cudaFuncAttributeMaxDynamicSharedMemorySize, SMEM_DYN);
    cudaFuncSetAttribute(k_gemm_mma<DOUT>, cudaFuncAttributeMaxDynamicSharedMemorySize, SMEM_DYN);

    // Fork: CSR build on s1, concurrent with prepW + GEMM1 on the capture stream.
    cudaStream_t s1;
    cudaStreamCreate(&s1);
    cudaEvent_t eFork, eJoin;
    cudaEventCreateWithFlags(&eFork, cudaEventDisableTiming);
    cudaEventCreateWithFlags(&eJoin, cudaEventDisableTiming);

    cudaEventRecord(eFork, 0);
    cudaStreamWaitEvent(s1, eFork, 0);

    // Branch B (s1): CSR build
    cudaMemsetAsync(degp, 0, NN * sizeof(int), s1);
    k_deg_count<<<(NE + 255) / 256, 256, 0, s1>>>(dst);
    k_scan<<<1, 1024, 0, s1>>>();
    k_fill<<<(NE + 255) / 256, 256, 0, s1>>>(src, dst);
    cudaEventRecord(eJoin, s1);

    // Branch A (capture stream): weight prep + GEMM1
    k_prepW<<<(KDIM * DHID + KDIM * DOUT + 255) / 256, 256>>>(W1, W2);
    k_gemm_mma<DHID><<<dim3((NN + 127) / 128, DHID / 128), 256, SMEM_DYN>>>(z, w1h, w1l, xs1, NN);

    // Join
    cudaStreamWaitEvent(0, eJoin, 0);

    k_aggregate<DHID / 4, true><<<(NN * 32 + 255) / 256, 256>>>(xs1, b1, h);

    k_gemm_mma<DOUT><<<dim3((NN + 127) / 128, DOUT / 128), 256, SMEM_DYN>>>(h, w2h, w2l, xs2, NN);
    k_aggregate<DOUT / 4, false><<<(NN * 32 + 255) / 256, 256>>>(xs2, b2, out);
}

// round 7
// speedup vs baseline: 2.1648x; 1.0855x over previous
#include <cuda_runtime.h>
#include <cuda_bf16.h>
#include <cuda_fp16.h>
#include <cstdint>

#define NN 50000
#define NE 800000
#define DHID 256
#define DOUT 128
#define KDIM 256

// ---------------- scratch (__device__ globals; no allocation allowed) -------
__device__ int   g_deg[NN];
__device__ int   g_off[NN + 1];
__device__ int   g_cur[NN];
__device__ float g_dinv[NN];
__device__ int   g_esrc[NE];
__device__ __half g_xs1[(size_t)NN * DHID];
__device__ float  g_h[(size_t)NN * DHID];
__device__ __half g_xs2[(size_t)NN * DOUT];
__device__ __nv_bfloat16 g_w1h[KDIM * DHID];   // [n][k] transposed, bf16 hi
__device__ __nv_bfloat16 g_w1l[KDIM * DHID];   // bf16 lo
__device__ __nv_bfloat16 g_w2h[KDIM * DOUT];
__device__ __nv_bfloat16 g_w2l[KDIM * DOUT];

// ---------------- helpers ----------------------------------------------------
__device__ __forceinline__ uint32_t smem_u32(const void* p) {
    uint32_t a;
    asm("{ .reg .u64 t; cvta.to.shared.u64 t, %1; cvt.u32.u64 %0, t; }" : "=r"(a) : "l"(p));
    return a;
}
#define SW128(off) ((off) ^ (((off) >> 3) & 0x70))

__device__ __forceinline__ void cp_async16(uint32_t smem, const void* g) {
    asm volatile("cp.async.cg.shared.global [%0], [%1], 16;" :: "r"(smem), "l"(g));
}
__device__ __forceinline__ void cp_commit() {
    asm volatile("cp.async.commit_group;" ::: "memory");
}
template <int N>
__device__ __forceinline__ void cp_wait() {
    asm volatile("cp.async.wait_group %0;" :: "n"(N) : "memory");
}
__device__ __forceinline__ void ldsm_x4(uint32_t addr, uint32_t* r) {
    asm volatile("ldmatrix.sync.aligned.m8n8.x4.shared.b16 {%0,%1,%2,%3}, [%4];"
                 : "=r"(r[0]), "=r"(r[1]), "=r"(r[2]), "=r"(r[3]) : "r"(addr));
}
__device__ __forceinline__ void mma_bf16(float* d, const uint32_t* a, uint32_t b0, uint32_t b1) {
    asm volatile("mma.sync.aligned.m16n8k16.row.col.f32.bf16.bf16.f32 "
                 "{%0,%1,%2,%3}, {%4,%5,%6,%7}, {%8,%9}, {%0,%1,%2,%3};"
                 : "+f"(d[0]), "+f"(d[1]), "+f"(d[2]), "+f"(d[3])
                 : "r"(a[0]), "r"(a[1]), "r"(a[2]), "r"(a[3]), "r"(b0), "r"(b1));
}

__device__ __forceinline__ void split4(float4 v, uint2& hi, uint2& lo) {
    __nv_bfloat16 hx = __float2bfloat16(v.x), hy = __float2bfloat16(v.y);
    __nv_bfloat16 hz = __float2bfloat16(v.z), hw = __float2bfloat16(v.w);
    __nv_bfloat16 lx = __float2bfloat16(v.x - __bfloat162float(hx));
    __nv_bfloat16 ly = __float2bfloat16(v.y - __bfloat162float(hy));
    __nv_bfloat16 lz = __float2bfloat16(v.z - __bfloat162float(hz));
    __nv_bfloat16 lw = __float2bfloat16(v.w - __bfloat162float(hw));
    __nv_bfloat162 h0 = __nv_bfloat162(hx, hy), h1 = __nv_bfloat162(hz, hw);
    __nv_bfloat162 l0 = __nv_bfloat162(lx, ly), l1 = __nv_bfloat162(lz, lw);
    hi.x = *(uint32_t*)&h0; hi.y = *(uint32_t*)&h1;
    lo.x = *(uint32_t*)&l0; lo.y = *(uint32_t*)&l1;
}

// ---------------- CSR build --------------------------------------------------
__global__ void k_deg_count(const int* __restrict__ dst) {
    int i = blockIdx.x * blockDim.x + threadIdx.x;
    if (i < NE) atomicAdd(&g_deg[dst[i]], 1);
}
__global__ void k_scan() {
    __shared__ int sh[1024];
    const int C = 49;
    int t = threadIdx.x;
    int start = t * C;
    int stop = start + C < NN ? start + C : NN;
    int s = 0;
    for (int i = start; i < stop; i++) s += g_deg[i];
    sh[t] = s;
    __syncthreads();
    for (int d = 1; d < 1024; d <<= 1) {
        int add = (t >= d) ? sh[t - d] : 0;
        __syncthreads();
        sh[t] += add;
        __syncthreads();
    }
    int run = sh[t] - s;
    for (int i = start; i < stop; i++) {
        g_off[i] = run;
        g_cur[i] = run;
        int dg = g_deg[i];
        run += dg;
        g_dinv[i] = rsqrtf((float)(dg + 1));
    }
    if (t == 0) g_off[NN] = NE;
}
__global__ void k_fill(const int* __restrict__ src, const int* __restrict__ dst) {
    int e = blockIdx.x * blockDim.x + threadIdx.x;
    if (e >= NE) return;
    int d = dst[e];
    int pos = atomicAdd(&g_cur[d], 1);
    g_esrc[pos] = src[e];
}

// ---------------- weight transpose + bf16 split -------------------------------
__global__ void k_prepW(const float* __restrict__ W1, const float* __restrict__ W2) {
    int i = blockIdx.x * blockDim.x + threadIdx.x;
    if (i < KDIM * DHID) {
        int k = i >> 8, n = i & 255;
        float v = W1[i];
        __nv_bfloat16 hb = __float2bfloat16(v);
        g_w1h[n * KDIM + k] = hb;
        g_w1l[n * KDIM + k] = __float2bfloat16(v - __bfloat162float(hb));
    }
    int j = i - KDIM * DHID;
    if (j >= 0 && j < KDIM * DOUT) {
        int k = j >> 7, n = j & 127;
        float v = W2[j];
        __nv_bfloat16 hb = __float2bfloat16(v);
        g_w2h[n * KDIM + k] = hb;
        g_w2l[n * KDIM + k] = __float2bfloat16(v - __bfloat162float(hb));
    }
}

// ---------------- mma.sync bf16-split GEMM: xs(fp16) = A @ B^T ----------------
#define STAGE 65536
#define SMEM_DYN (2 * STAGE)

template <int NTOT>
__global__ void __launch_bounds__(256, 1) k_gemm_mma(
    const float* __restrict__ A, const __nv_bfloat16* __restrict__ Bhg,
    const __nv_bfloat16* __restrict__ Blg, __half* __restrict__ xs, int M) {
    extern __shared__ char smraw[];
    uint32_t sb = smem_u32(smraw);
    int tid = threadIdx.x;
    int wid = tid >> 5, lane = tid & 31;
    int wm = wid & 3, wn = wid >> 2;
    int bm = blockIdx.x * 128;
    int bn = blockIdx.y * 128;

    float acc[2][8][4];
#pragma unroll
    for (int a = 0; a < 2; a++)
#pragma unroll
        for (int b = 0; b < 8; b++)
#pragma unroll
            for (int c = 0; c < 4; c++) acc[a][b][c] = 0.f;

    auto issueB = [&](int c, uint32_t stage) {
#pragma unroll
        for (int i = 0; i < 4; i++) {
            int task = i * 256 + tid;
            int row = task >> 3;
            int u = task & 7;
            uint32_t off = SW128((uint32_t)(row * 128 + u * 16));
            size_t gsrc = (size_t)(bn + row) * KDIM + c * 64 + u * 8;
            cp_async16(stage + 32768 + off, Bhg + gsrc);
            cp_async16(stage + 49152 + off, Blg + gsrc);
        }
    };
    auto copyA = [&](int c, uint32_t stage) {
#pragma unroll
        for (int i = 0; i < 8; i++) {
            int task = i * 256 + tid;
            int row = task >> 4;
            int c4 = task & 15;
            float4 v = make_float4(0.f, 0.f, 0.f, 0.f);
            if (bm + row < M)
                v = *(const float4*)(A + (size_t)(bm + row) * KDIM + c * 64 + c4 * 4);
            uint2 hi, lo;
            split4(v, hi, lo);
            uint32_t off = SW128((uint32_t)(row * 128 + c4 * 8));
            *(uint2*)(smraw + (stage - sb) + off) = hi;
            *(uint2*)(smraw + (stage - sb) + 16384 + off) = lo;
        }
    };

    issueB(0, sb);
    cp_commit();

    for (int c = 0; c < 4; c++) {
        uint32_t stage = sb + (uint32_t)(c & 1) * STAGE;
        copyA(c, stage);
        if (c < 3) {
            issueB(c + 1, sb + (uint32_t)((c + 1) & 1) * STAGE);
            cp_commit();
            cp_wait<1>();
        } else {
            cp_wait<0>();
        }
        __syncthreads();

#pragma unroll
        for (int ks = 0; ks < 4; ks++) {
            uint32_t ah[2][4], al[2][4];
            uint32_t acol = (uint32_t)(ks * 32 + (lane >> 4) * 16);
#pragma unroll
            for (int mt = 0; mt < 2; mt++) {
                uint32_t arow = (uint32_t)(wm * 32 + mt * 16 + (lane & 15));
                uint32_t aoff = SW128(arow * 128 + acol);
                ldsm_x4(stage + aoff, ah[mt]);
                ldsm_x4(stage + 16384 + aoff, al[mt]);
            }
            uint32_t bcol = (uint32_t)(ks * 32 + ((lane >> 3) & 1) * 16);
#pragma unroll
            for (int p = 0; p < 4; p++) {
                uint32_t brow = (uint32_t)(wn * 64 + p * 16 + (lane & 7) + ((lane >> 4) << 3));
                uint32_t boff = SW128(brow * 128 + bcol);
                uint32_t bh[4], bl[4];
                ldsm_x4(stage + 32768 + boff, bh);
                ldsm_x4(stage + 49152 + boff, bl);
#pragma unroll
                for (int mt = 0; mt < 2; mt++) {
#pragma unroll
                    for (int q = 0; q < 2; q++) {
                        float* d = acc[mt][p * 2 + q];
                        mma_bf16(d, ah[mt], bh[2 * q], bh[2 * q + 1]);
                        mma_bf16(d, al[mt], bh[2 * q], bh[2 * q + 1]);
                        mma_bf16(d, ah[mt], bl[2 * q], bl[2 * q + 1]);
                    }
                }
            }
        }
        if (c < 3) __syncthreads();
    }

#pragma unroll
    for (int mt = 0; mt < 2; mt++) {
        int r0 = bm + wm * 32 + mt * 16 + (lane >> 2);
        int r1 = r0 + 8;
#pragma unroll
        for (int nt = 0; nt < 8; nt++) {
            int col = bn + wn * 64 + nt * 8 + (lane & 3) * 2;
            float* d = acc[mt][nt];
            if (r0 < M) *(__half2*)(xs + (size_t)r0 * NTOT + col) = __floats2half2_rn(d[0], d[1]);
            if (r1 < M) *(__half2*)(xs + (size_t)r1 * NTOT + col) = __floats2half2_rn(d[2], d[3]);
        }
    }
}

// ---------------- CSR aggregate (one warp per node, fp16 gather) --------------
// D halves per row; each lane owns C = D/32 consecutive columns (one 2C-byte load).
template <int D, bool RELU>
__global__ void k_aggregate(const __half* __restrict__ xs,
                            const float* __restrict__ bias,
                            float* __restrict__ outp) {
    int w = (blockIdx.x * blockDim.x + threadIdx.x) >> 5;
    int lane = threadIdx.x & 31;
    if (w >= NN) return;
    constexpr int C = D / 32;   // 8 (D=256) or 4 (D=128)
    constexpr int W = C / 2;    // uint32 words per lane

    auto loadrow = [&](int node, uint32_t (&uw)[W]) {
        const __half* rp = xs + (size_t)node * D + lane * C;
        if (C == 8) {
            uint4 t = __ldg((const uint4*)rp);
            uw[0] = t.x; uw[1] = t.y; uw[2] = t.z; uw[3] = t.w;
        } else {
            uint2 t = __ldg((const uint2*)rp);
            uw[0] = t.x; uw[1] = t.y;
        }
    };

    float dvw = g_dinv[w];
    float acc[C], acc2[C];
    {
        uint32_t uw[W];
        loadrow(w, uw);
#pragma unroll
        for (int j = 0; j < W; j++) {
            float2 f = __half22float2(*(__half2*)&uw[j]);
            acc[2 * j] = f.x * dvw;
            acc[2 * j + 1] = f.y * dvw;
            acc2[2 * j] = 0.f;
            acc2[2 * j + 1] = 0.f;
        }
    }

    int beg = g_off[w], end = g_off[w + 1];
    int i = beg;
    for (; i + 1 < end; i += 2) {
        int s0 = __ldg(&g_esrc[i]);
        int s1 = __ldg(&g_esrc[i + 1]);
        float ds0 = __ldg(&g_dinv[s0]);
        float ds1 = __ldg(&g_dinv[s1]);
        uint32_t u0[W], u1[W];
        loadrow(s0, u0);
        loadrow(s1, u1);
#pragma unroll
        for (int j = 0; j < W; j++) {
            float2 f0 = __half22float2(*(__half2*)&u0[j]);
            float2 f1 = __half22float2(*(__half2*)&u1[j]);
            acc[2 * j]      = fmaf(f0.x, ds0, acc[2 * j]);
            acc[2 * j + 1]  = fmaf(f0.y, ds0, acc[2 * j + 1]);
            acc2[2 * j]     = fmaf(f1.x, ds1, acc2[2 * j]);
            acc2[2 * j + 1] = fmaf(f1.y, ds1, acc2[2 * j + 1]);
        }
    }
    if (i < end) {
        int s0 = __ldg(&g_esrc[i]);
        float ds0 = __ldg(&g_dinv[s0]);
        uint32_t u0[W];
        loadrow(s0, u0);
#pragma unroll
        for (int j = 0; j < W; j++) {
            float2 f0 = __half22float2(*(__half2*)&u0[j]);
            acc[2 * j]     = fmaf(f0.x, ds0, acc[2 * j]);
            acc[2 * j + 1] = fmaf(f0.y, ds0, acc[2 * j + 1]);
        }
    }

    float* orow = outp + (size_t)w * D + lane * C;
    const float* bp = bias + lane * C;
#pragma unroll
    for (int v = 0; v < C / 4; v++) {
        float4 b = __ldg((const float4*)bp + v);
        float4 o;
        o.x = dvw * (acc[4 * v + 0] + acc2[4 * v + 0]) + b.x;
        o.y = dvw * (acc[4 * v + 1] + acc2[4 * v + 1]) + b.y;
        o.z = dvw * (acc[4 * v + 2] + acc2[4 * v + 2]) + b.z;
        o.w = dvw * (acc[4 * v + 3] + acc2[4 * v + 3]) + b.w;
        if (RELU) {
            o.x = fmaxf(o.x, 0.f); o.y = fmaxf(o.y, 0.f);
            o.z = fmaxf(o.z, 0.f); o.w = fmaxf(o.w, 0.f);
        }
        *((float4*)orow + v) = o;
    }
}

// ---------------- launch ------------------------------------------------------
extern "C" void kernel_launch(void* const* d_in, const int* in_sizes, int n_in,
                              void* d_out, int out_size) {
    const float* z  = (const float*)d_in[0];
    const int*   ei = (const int*)d_in[1];
    const float* W1 = (const float*)d_in[2];
    const float* b1 = (const float*)d_in[3];
    const float* W2 = (const float*)d_in[4];
    const float* b2 = (const float*)d_in[5];
    const int* src = ei;
    const int* dst = ei + NE;
    float* out = (float*)d_out;

    __half *xs1, *xs2;
    float* h;
    int* degp;
    __nv_bfloat16 *w1h, *w1l, *w2h, *w2l;
    cudaGetSymbolAddress((void**)&xs1, g_xs1);
    cudaGetSymbolAddress((void**)&h,   g_h);
    cudaGetSymbolAddress((void**)&xs2, g_xs2);
    cudaGetSymbolAddress((void**)&degp, g_deg);
    cudaGetSymbolAddress((void**)&w1h, g_w1h);
    cudaGetSymbolAddress((void**)&w1l, g_w1l);
    cudaGetSymbolAddress((void**)&w2h, g_w2h);
    cudaGetSymbolAddress((void**)&w2l, g_w2l);

    cudaFuncSetAttribute(k_gemm_mma<DHID>, cudaFuncAttributeMaxDynamicSharedMemorySize, SMEM_DYN);
    cudaFuncSetAttribute(k_gemm_mma<DOUT>, cudaFuncAttributeMaxDynamicSharedMemorySize, SMEM_DYN);

    // Fork: CSR build on s1, concurrent with prepW + GEMM1 on the capture stream.
    cudaStream_t s1;
    cudaStreamCreate(&s1);
    cudaEvent_t eFork, eJoin;
    cudaEventCreateWithFlags(&eFork, cudaEventDisableTiming);
    cudaEventCreateWithFlags(&eJoin, cudaEventDisableTiming);

    cudaEventRecord(eFork, 0);
    cudaStreamWaitEvent(s1, eFork, 0);

    // Branch B (s1): CSR build
    cudaMemsetAsync(degp, 0, NN * sizeof(int), s1);
    k_deg_count<<<(NE + 255) / 256, 256, 0, s1>>>(dst);
    k_scan<<<1, 1024, 0, s1>>>();
    k_fill<<<(NE + 255) / 256, 256, 0, s1>>>(src, dst);
    cudaEventRecord(eJoin, s1);

    // Branch A (capture stream): weight prep + GEMM1
    k_prepW<<<(KDIM * DHID + KDIM * DOUT + 255) / 256, 256>>>(W1, W2);
    k_gemm_mma<DHID><<<dim3((NN + 127) / 128, DHID / 128), 256, SMEM_DYN>>>(z, w1h, w1l, xs1, NN);

    // Join
    cudaStreamWaitEvent(0, eJoin, 0);

    k_aggregate<DHID, true><<<(NN * 32 + 255) / 256, 256>>>(xs1, b1, h);

    k_gemm_mma<DOUT><<<dim3((NN + 127) / 128, DOUT / 128), 256, SMEM_DYN>>>(h, w2h, w2l, xs2, NN);
    k_aggregate<DOUT, false><<<(NN * 32 + 255) / 256, 256>>>(xs2, b2, out);
}

// round 8
// speedup vs baseline: 2.2127x; 1.0221x over previous
#include <cuda_runtime.h>
#include <cuda_bf16.h>
#include <cuda_fp16.h>
#include <cstdint>

#define NN 50000
#define NE 800000
#define DHID 256
#define DOUT 128
#define KDIM 256

// ---------------- scratch (__device__ globals; no allocation allowed) -------
__device__ int   g_deg[NN];
__device__ int   g_off[NN + 1];
__device__ int   g_cur[NN];
__device__ float g_dinv[NN];
__device__ int   g_esrc[NE];
__device__ __half g_xs1[(size_t)NN * DHID];
__device__ __half g_xs2[(size_t)NN * DOUT];
__device__ __nv_bfloat16 g_a1h[(size_t)NN * KDIM];   // z split hi
__device__ __nv_bfloat16 g_a1l[(size_t)NN * KDIM];   // z split lo
__device__ __nv_bfloat16 g_hh[(size_t)NN * DHID];    // h split hi
__device__ __nv_bfloat16 g_hl[(size_t)NN * DHID];    // h split lo
__device__ __nv_bfloat16 g_w1h[KDIM * DHID];         // [n][k] transposed, bf16 hi
__device__ __nv_bfloat16 g_w1l[KDIM * DHID];
__device__ __nv_bfloat16 g_w2h[KDIM * DOUT];
__device__ __nv_bfloat16 g_w2l[KDIM * DOUT];

// ---------------- helpers ----------------------------------------------------
__device__ __forceinline__ uint32_t smem_u32(const void* p) {
    uint32_t a;
    asm("{ .reg .u64 t; cvta.to.shared.u64 t, %1; cvt.u32.u64 %0, t; }" : "=r"(a) : "l"(p));
    return a;
}
#define SW64(o) ((o) ^ (((o) >> 3) & 0x30))

__device__ __forceinline__ void cp_async16(uint32_t smem, const void* g) {
    asm volatile("cp.async.cg.shared.global [%0], [%1], 16;" :: "r"(smem), "l"(g));
}
__device__ __forceinline__ void cp_async16_z(uint32_t smem, const void* g, bool valid) {
    int sz = valid ? 16 : 0;
    asm volatile("cp.async.cg.shared.global [%0], [%1], 16, %2;" :: "r"(smem), "l"(g), "r"(sz));
}
__device__ __forceinline__ void cp_commit() {
    asm volatile("cp.async.commit_group;" ::: "memory");
}
template <int N>
__device__ __forceinline__ void cp_wait() {
    asm volatile("cp.async.wait_group %0;" :: "n"(N) : "memory");
}
__device__ __forceinline__ void ldsm_x4(uint32_t addr, uint32_t* r) {
    asm volatile("ldmatrix.sync.aligned.m8n8.x4.shared.b16 {%0,%1,%2,%3}, [%4];"
                 : "=r"(r[0]), "=r"(r[1]), "=r"(r[2]), "=r"(r[3]) : "r"(addr));
}
__device__ __forceinline__ void mma_bf16(float* d, const uint32_t* a, uint32_t b0, uint32_t b1) {
    asm volatile("mma.sync.aligned.m16n8k16.row.col.f32.bf16.bf16.f32 "
                 "{%0,%1,%2,%3}, {%4,%5,%6,%7}, {%8,%9}, {%0,%1,%2,%3};"
                 : "+f"(d[0]), "+f"(d[1]), "+f"(d[2]), "+f"(d[3])
                 : "r"(a[0]), "r"(a[1]), "r"(a[2]), "r"(a[3]), "r"(b0), "r"(b1));
}

// ---------------- CSR build --------------------------------------------------
__global__ void k_deg_count(const int* __restrict__ dst) {
    int i = blockIdx.x * blockDim.x + threadIdx.x;
    if (i < NE) atomicAdd(&g_deg[dst[i]], 1);
}
__global__ void k_scan() {
    __shared__ int sh[1024];
    const int C = 49;
    int t = threadIdx.x;
    int start = t * C;
    int stop = start + C < NN ? start + C : NN;
    int s = 0;
    for (int i = start; i < stop; i++) s += g_deg[i];
    sh[t] = s;
    __syncthreads();
    for (int d = 1; d < 1024; d <<= 1) {
        int add = (t >= d) ? sh[t - d] : 0;
        __syncthreads();
        sh[t] += add;
        __syncthreads();
    }
    int run = sh[t] - s;
    for (int i = start; i < stop; i++) {
        g_off[i] = run;
        g_cur[i] = run;
        int dg = g_deg[i];
        run += dg;
        g_dinv[i] = rsqrtf((float)(dg + 1));
    }
    if (t == 0) g_off[NN] = NE;
}
__global__ void k_fill(const int* __restrict__ src, const int* __restrict__ dst) {
    int e = blockIdx.x * blockDim.x + threadIdx.x;
    if (e >= NE) return;
    int d = dst[e];
    int pos = atomicAdd(&g_cur[d], 1);
    g_esrc[pos] = src[e];
}

// ---------------- weight transpose + bf16 split -------------------------------
__global__ void k_prepW(const float* __restrict__ W1, const float* __restrict__ W2) {
    int i = blockIdx.x * blockDim.x + threadIdx.x;
    if (i < KDIM * DHID) {
        int k = i >> 8, n = i & 255;
        float v = W1[i];
        __nv_bfloat16 hb = __float2bfloat16(v);
        g_w1h[n * KDIM + k] = hb;
        g_w1l[n * KDIM + k] = __float2bfloat16(v - __bfloat162float(hb));
    }
    int j = i - KDIM * DHID;
    if (j >= 0 && j < KDIM * DOUT) {
        int k = j >> 7, n = j & 127;
        float v = W2[j];
        __nv_bfloat16 hb = __float2bfloat16(v);
        g_w2h[n * KDIM + k] = hb;
        g_w2l[n * KDIM + k] = __float2bfloat16(v - __bfloat162float(hb));
    }
}

// ---------------- A split: z -> bf16 hi/lo ------------------------------------
__global__ void k_prepA(const float* __restrict__ A) {
    int i = blockIdx.x * blockDim.x + threadIdx.x;   // float4 index
    if (i >= NN * (KDIM / 4)) return;
    float4 v = *((const float4*)A + i);
    __nv_bfloat16 hx = __float2bfloat16(v.x), hy = __float2bfloat16(v.y);
    __nv_bfloat16 hz = __float2bfloat16(v.z), hw = __float2bfloat16(v.w);
    __nv_bfloat162 h0(hx, hy), h1(hz, hw);
    __nv_bfloat162 l0(__float2bfloat16(v.x - __bfloat162float(hx)),
                      __float2bfloat16(v.y - __bfloat162float(hy)));
    __nv_bfloat162 l1(__float2bfloat16(v.z - __bfloat162float(hz)),
                      __float2bfloat16(v.w - __bfloat162float(hw)));
    uint2 hu, lu;
    hu.x = *(uint32_t*)&h0; hu.y = *(uint32_t*)&h1;
    lu.x = *(uint32_t*)&l0; lu.y = *(uint32_t*)&l1;
    *((uint2*)g_a1h + i) = hu;
    *((uint2*)g_a1l + i) = lu;
}

// ---------------- async bf16-split GEMM: xs(fp16) = A @ B^T -------------------
// CTA 128x128, 8 warps (4m x 2n). K chunks of 32, 3-stage cp.async ring.
// Stage: Ah@0 (8KB), Al@8K, Bh@16K, Bl@24K. 64B rows, SW64 swizzle.
#define CH 32
#define NCH (KDIM / CH)
#define STAGE_B 32768
#define NSTAGE 3
#define SMEM_DYN (NSTAGE * STAGE_B)

template <int NTOT>
__global__ void __launch_bounds__(256) k_gemm_mma(
    const __nv_bfloat16* __restrict__ Ahg, const __nv_bfloat16* __restrict__ Alg,
    const __nv_bfloat16* __restrict__ Bhg, const __nv_bfloat16* __restrict__ Blg,
    __half* __restrict__ xs, int M) {
    extern __shared__ char smraw[];
    uint32_t sb = smem_u32(smraw);
    int tid = threadIdx.x;
    int wid = tid >> 5, lane = tid & 31;
    int wm = wid & 3, wn = wid >> 2;
    int bm = blockIdx.x * 128;
    int bn = blockIdx.y * 128;

    float acc[2][8][4];
#pragma unroll
    for (int a = 0; a < 2; a++)
#pragma unroll
        for (int b = 0; b < 8; b++)
#pragma unroll
            for (int c = 0; c < 4; c++) acc[a][b][c] = 0.f;

    // issue chunk c into stage s: per matrix 8KB = 512 x 16B; 2 tasks/thread each
    auto issue = [&](int c, int s) {
        uint32_t st = sb + (uint32_t)s * STAGE_B;
#pragma unroll
        for (int i = 0; i < 2; i++) {
            int task = i * 256 + tid;            // 0..511
            int row = task >> 2;                 // 0..127
            int u = task & 3;                    // 16B unit within 64B row
            uint32_t off = SW64((uint32_t)(row * 64 + u * 16));
            // A
            bool av = (bm + row) < M;
            size_t ga = (size_t)(bm + row) * KDIM + c * CH + u * 8;
            cp_async16_z(st + off, Ahg + ga, av);
            cp_async16_z(st + 8192 + off, Alg + ga, av);
            // B
            size_t gb = (size_t)(bn + row) * KDIM + c * CH + u * 8;
            cp_async16(st + 16384 + off, Bhg + gb);
            cp_async16(st + 24576 + off, Blg + gb);
        }
    };

#pragma unroll
    for (int c = 0; c < NSTAGE; c++) { issue(c, c); cp_commit(); }

    for (int c = 0; c < NCH; c++) {
        uint32_t st = sb + (uint32_t)(c % NSTAGE) * STAGE_B;
        cp_wait<NSTAGE - 1>();
        __syncthreads();

#pragma unroll
        for (int ks = 0; ks < CH / 16; ks++) {
            uint32_t ah[2][4], al[2][4];
#pragma unroll
            for (int mt = 0; mt < 2; mt++) {
                uint32_t arow = (uint32_t)(wm * 32 + mt * 16 + (lane & 15));
                uint32_t aoff = SW64(arow * 64 + (uint32_t)(ks * 32) + ((lane >> 4) << 4));
                ldsm_x4(st + aoff, ah[mt]);
                ldsm_x4(st + 8192 + aoff, al[mt]);
            }
#pragma unroll
            for (int p = 0; p < 4; p++) {
                uint32_t brow = (uint32_t)(wn * 64 + p * 16 + (lane & 7) + ((lane >> 4) << 3));
                uint32_t boff = SW64(brow * 64 + (uint32_t)(ks * 32) + (((lane >> 3) & 1) << 4));
                uint32_t bh[4], bl[4];
                ldsm_x4(st + 16384 + boff, bh);
                ldsm_x4(st + 24576 + boff, bl);
#pragma unroll
                for (int mt = 0; mt < 2; mt++) {
#pragma unroll
                    for (int q = 0; q < 2; q++) {
                        float* d = acc[mt][p * 2 + q];
                        mma_bf16(d, ah[mt], bh[2 * q], bh[2 * q + 1]);
                        mma_bf16(d, al[mt], bh[2 * q], bh[2 * q + 1]);
                        mma_bf16(d, ah[mt], bl[2 * q], bl[2 * q + 1]);
                    }
                }
            }
        }
        __syncthreads();
        if (c + NSTAGE < NCH) issue(c + NSTAGE, c % NSTAGE);
        cp_commit();
    }

#pragma unroll
    for (int mt = 0; mt < 2; mt++) {
        int r0 = bm + wm * 32 + mt * 16 + (lane >> 2);
        int r1 = r0 + 8;
#pragma unroll
        for (int nt = 0; nt < 8; nt++) {
            int col = bn + wn * 64 + nt * 8 + (lane & 3) * 2;
            float* d = acc[mt][nt];
            if (r0 < M) *(__half2*)(xs + (size_t)r0 * NTOT + col) = __floats2half2_rn(d[0], d[1]);
            if (r1 < M) *(__half2*)(xs + (size_t)r1 * NTOT + col) = __floats2half2_rn(d[2], d[3]);
        }
    }
}

// ---------------- CSR aggregate (warp/node, fp16 gather, batch-4 prefetch) ----
// SPLIT: write bf16 hi/lo (layer 1 -> h). else: write fp32 (final out).
template <int D, bool RELU, bool SPLIT>
__global__ void k_aggregate(const __half* __restrict__ xs,
                            const float* __restrict__ bias,
                            float* __restrict__ outf,
                            __nv_bfloat16* __restrict__ oh,
                            __nv_bfloat16* __restrict__ ol) {
    int w = (blockIdx.x * blockDim.x + threadIdx.x) >> 5;
    int lane = threadIdx.x & 31;
    if (w >= NN) return;
    constexpr int C = D / 32;   // halves per lane: 8 (D=256) or 4 (D=128)
    constexpr int W = C / 2;    // uint32 words per lane

    auto loadrow = [&](int node, uint32_t (&uw)[W]) {
        const __half* rp = xs + (size_t)node * D + lane * C;
        if (C == 8) {
            uint4 t = __ldg((const uint4*)rp);
            uw[0] = t.x; uw[1] = t.y; uw[2] = t.z; uw[3] = t.w;
        } else {
            uint2 t = __ldg((const uint2*)rp);
            uw[0] = t.x; uw[1] = t.y;
        }
    };
    auto fma_row = [&](const uint32_t (&uw)[W], float ds, float (&a)[C]) {
#pragma unroll
        for (int j = 0; j < W; j++) {
            float2 f = __half22float2(*(__half2*)&uw[j]);
            a[2 * j] = fmaf(f.x, ds, a[2 * j]);
            a[2 * j + 1] = fmaf(f.y, ds, a[2 * j + 1]);
        }
    };

    float dvw = g_dinv[w];
    float acc[C], acc2[C];
    {
        uint32_t uw[W];
        loadrow(w, uw);
#pragma unroll
        for (int j = 0; j < W; j++) {
            float2 f = __half22float2(*(__half2*)&uw[j]);
            acc[2 * j] = f.x * dvw;
            acc[2 * j + 1] = f.y * dvw;
            acc2[2 * j] = 0.f;
            acc2[2 * j + 1] = 0.f;
        }
    }

    int beg = g_off[w], end = g_off[w + 1];
    int i = beg;
    for (; i + 4 <= end; i += 4) {
        int s0 = __ldg(&g_esrc[i]);
        int s1 = __ldg(&g_esrc[i + 1]);
        int s2 = __ldg(&g_esrc[i + 2]);
        int s3 = __ldg(&g_esrc[i + 3]);
        float d0 = __ldg(&g_dinv[s0]);
        float d1 = __ldg(&g_dinv[s1]);
        float d2 = __ldg(&g_dinv[s2]);
        float d3 = __ldg(&g_dinv[s3]);
        uint32_t u0[W], u1[W], u2[W], u3[W];
        loadrow(s0, u0);
        loadrow(s1, u1);
        loadrow(s2, u2);
        loadrow(s3, u3);
        fma_row(u0, d0, acc);
        fma_row(u1, d1, acc2);
        fma_row(u2, d2, acc);
        fma_row(u3, d3, acc2);
    }
    for (; i < end; i++) {
        int s0 = __ldg(&g_esrc[i]);
        float d0 = __ldg(&g_dinv[s0]);
        uint32_t u0[W];
        loadrow(s0, u0);
        fma_row(u0, d0, acc);
    }

    const float* bp = bias + lane * C;
    float o[C];
#pragma unroll
    for (int v = 0; v < C / 4; v++) {
        float4 b = __ldg((const float4*)bp + v);
        o[4 * v + 0] = dvw * (acc[4 * v + 0] + acc2[4 * v + 0]) + b.x;
        o[4 * v + 1] = dvw * (acc[4 * v + 1] + acc2[4 * v + 1]) + b.y;
        o[4 * v + 2] = dvw * (acc[4 * v + 2] + acc2[4 * v + 2]) + b.z;
        o[4 * v + 3] = dvw * (acc[4 * v + 3] + acc2[4 * v + 3]) + b.w;
    }
    if (RELU) {
#pragma unroll
        for (int c = 0; c < C; c++) o[c] = fmaxf(o[c], 0.f);
    }

    if (SPLIT) {
        uint32_t hw_[W], lw_[W];
#pragma unroll
        for (int j = 0; j < W; j++) {
            __nv_bfloat16 h0 = __float2bfloat16(o[2 * j]);
            __nv_bfloat16 h1 = __float2bfloat16(o[2 * j + 1]);
            __nv_bfloat162 hp(h0, h1);
            __nv_bfloat162 lp(__float2bfloat16(o[2 * j] - __bfloat162float(h0)),
                              __float2bfloat16(o[2 * j + 1] - __bfloat162float(h1)));
            hw_[j] = *(uint32_t*)&hp;
            lw_[j] = *(uint32_t*)&lp;
        }
        __nv_bfloat16* hp = oh + (size_t)w * D + lane * C;
        __nv_bfloat16* lp = ol + (size_t)w * D + lane * C;
        if (C == 8) {
            *(uint4*)hp = make_uint4(hw_[0], hw_[1], hw_[2], hw_[3]);
            *(uint4*)lp = make_uint4(lw_[0], lw_[1], lw_[2], lw_[3]);
        } else {
            *(uint2*)hp = make_uint2(hw_[0], hw_[1]);
            *(uint2*)lp = make_uint2(lw_[0], lw_[1]);
        }
    } else {
        float* orow = outf + (size_t)w * D + lane * C;
#pragma unroll
        for (int v = 0; v < C / 4; v++)
            *((float4*)orow + v) = make_float4(o[4 * v + 0], o[4 * v + 1], o[4 * v + 2], o[4 * v + 3]);
    }
}

// ---------------- launch ------------------------------------------------------
extern "C" void kernel_launch(void* const* d_in, const int* in_sizes, int n_in,
                              void* d_out, int out_size) {
    const float* z  = (const float*)d_in[0];
    const int*   ei = (const int*)d_in[1];
    const float* W1 = (const float*)d_in[2];
    const float* b1 = (const float*)d_in[3];
    const float* W2 = (const float*)d_in[4];
    const float* b2 = (const float*)d_in[5];
    const int* src = ei;
    const int* dst = ei + NE;
    float* out = (float*)d_out;

    __half *xs1, *xs2;
    int* degp;
    __nv_bfloat16 *a1h, *a1l, *hh, *hl, *w1h, *w1l, *w2h, *w2l;
    cudaGetSymbolAddress((void**)&xs1, g_xs1);
    cudaGetSymbolAddress((void**)&xs2, g_xs2);
    cudaGetSymbolAddress((void**)&degp, g_deg);
    cudaGetSymbolAddress((void**)&a1h, g_a1h);
    cudaGetSymbolAddress((void**)&a1l, g_a1l);
    cudaGetSymbolAddress((void**)&hh, g_hh);
    cudaGetSymbolAddress((void**)&hl, g_hl);
    cudaGetSymbolAddress((void**)&w1h, g_w1h);
    cudaGetSymbolAddress((void**)&w1l, g_w1l);
    cudaGetSymbolAddress((void**)&w2h, g_w2h);
    cudaGetSymbolAddress((void**)&w2l, g_w2l);

    cudaFuncSetAttribute(k_gemm_mma<DHID>, cudaFuncAttributeMaxDynamicSharedMemorySize, SMEM_DYN);
    cudaFuncSetAttribute(k_gemm_mma<DOUT>, cudaFuncAttributeMaxDynamicSharedMemorySize, SMEM_DYN);

    // Fork: CSR build on s1, concurrent with prep + GEMM1 on the capture stream.
    cudaStream_t s1;
    cudaStreamCreate(&s1);
    cudaEvent_t eFork, eJoin;
    cudaEventCreateWithFlags(&eFork, cudaEventDisableTiming);
    cudaEventCreateWithFlags(&eJoin, cudaEventDisableTiming);

    cudaEventRecord(eFork, 0);
    cudaStreamWaitEvent(s1, eFork, 0);

    // Branch B (s1): CSR build
    cudaMemsetAsync(degp, 0, NN * sizeof(int), s1);
    k_deg_count<<<(NE + 255) / 256, 256, 0, s1>>>(dst);
    k_scan<<<1, 1024, 0, s1>>>();
    k_fill<<<(NE + 255) / 256, 256, 0, s1>>>(src, dst);
    cudaEventRecord(eJoin, s1);

    // Branch A (capture stream): weight + A prep, then GEMM1
    k_prepW<<<(KDIM * DHID + KDIM * DOUT + 255) / 256, 256>>>(W1, W2);
    k_prepA<<<(NN * (KDIM / 4) + 255) / 256, 256>>>(z);
    k_gemm_mma<DHID><<<dim3((NN + 127) / 128, DHID / 128), 256, SMEM_DYN>>>(a1h, a1l, w1h, w1l, xs1, NN);

    // Join
    cudaStreamWaitEvent(0, eJoin, 0);

    k_aggregate<DHID, true, true><<<(NN * 32 + 255) / 256, 256>>>(xs1, b1, nullptr, hh, hl);

    k_gemm_mma<DOUT><<<dim3((NN + 127) / 128, DOUT / 128), 256, SMEM_DYN>>>(hh, hl, w2h, w2l, xs2, NN);
    k_aggregate<DOUT, false, false><<<(NN * 32 + 255) / 256, 256>>>(xs2, b2, out, nullptr, nullptr);
}